// round 3
// baseline (speedup 1.0000x reference)
#include <cuda_runtime.h>
#include <cstdint>

// ---------------------------------------------------------------------------
// Transcoder: pre = (x - bias) @ enc_w^T + enc_b ; top-k sparsify ; decode ; MSE
// T=4096, D_IN=4096, NF=32768, D_OUT=4096, k=64
// Round 3: Kahan-compensated encode GEMM (re-run after infra flake),
// double-buffered smem pipeline in the GEMM.
// ---------------------------------------------------------------------------

#define T_TOK 4096
#define DIN   4096
#define NFEAT 32768
#define DOUTD 4096
#define MAXK  128

__device__ float  g_xc[(size_t)T_TOK * DIN];
__device__ float  g_wT[(size_t)NFEAT * DOUTD];
__device__ int    g_selIdx[(size_t)T_TOK * MAXK];
__device__ float  g_selVal[(size_t)T_TOK * MAXK];
__device__ double g_partial[T_TOK];
__device__ float  g_preFB[(size_t)T_TOK * NFEAT];
__device__ float  g_predFB[(size_t)T_TOK * DOUTD];

// ---------------------------------------------------------------------------
__device__ __forceinline__ uint32_t f2k(float f) {
    uint32_t u = __float_as_uint(f);
    return (u & 0x80000000u) ? ~u : (u | 0x80000000u);
}
__device__ __forceinline__ float k2f(uint32_t u) {
    uint32_t v = (u & 0x80000000u) ? (u ^ 0x80000000u) : ~u;
    return __uint_as_float(v);
}

__device__ __forceinline__ int block_exscan512(int v, int* s16) {
    int tid  = threadIdx.x;
    int lane = tid & 31, wid = tid >> 5;
    int x = v;
    #pragma unroll
    for (int o = 1; o < 32; o <<= 1) {
        int y = __shfl_up_sync(0xffffffffu, x, o);
        if (lane >= o) x += y;
    }
    if (lane == 31) s16[wid] = x;
    __syncthreads();
    if (wid == 0) {
        int w = (lane < 16) ? s16[lane] : 0;
        #pragma unroll
        for (int o = 1; o < 16; o <<= 1) {
            int y = __shfl_up_sync(0xffffffffu, w, o);
            if (lane >= o) w += y;
        }
        if (lane < 16) s16[lane] = w;
    }
    __syncthreads();
    int base = wid ? s16[wid - 1] : 0;
    int r = base + x - v;
    __syncthreads();
    return r;
}

// ---------------------------------------------------------------------------
// 1) center
// ---------------------------------------------------------------------------
__global__ void center_kernel(const float4* __restrict__ x,
                              const float4* __restrict__ bias) {
    size_t n = (size_t)T_TOK * DIN / 4;
    for (size_t i = (size_t)blockIdx.x * blockDim.x + threadIdx.x; i < n;
         i += (size_t)gridDim.x * blockDim.x) {
        float4 a = x[i];
        float4 b = bias[i & (DIN / 4 - 1)];
        float4 r;
        r.x = a.x - b.x; r.y = a.y - b.y; r.z = a.z - b.z; r.w = a.w - b.w;
        ((float4*)g_xc)[i] = r;
    }
}

// ---------------------------------------------------------------------------
// 2) transpose dec_w -> g_wT [NFEAT, DOUTD]
// ---------------------------------------------------------------------------
__global__ void transpose_kernel(const float* __restrict__ W) {
    __shared__ float tile[32][33];
    int j0 = blockIdx.x * 32;
    int d0 = blockIdx.y * 32;
    int tx = threadIdx.x, ty0 = threadIdx.y;
    #pragma unroll
    for (int ty = ty0; ty < 32; ty += 8)
        tile[ty][tx] = W[(size_t)(d0 + ty) * NFEAT + j0 + tx];
    __syncthreads();
    #pragma unroll
    for (int ty = ty0; ty < 32; ty += 8)
        g_wT[(size_t)(j0 + ty) * DOUTD + d0 + tx] = tile[tx][ty];
}

// ---------------------------------------------------------------------------
// 3) near-exact GEMM: C[t,f] = sum_k x[t,k]*w[f,k] + enc_b[f]
//    BM=128, BN=64, BK=16; 256 threads; microtile 8x4; double-buffered smem.
//    16-k block products in fp32, Kahan-folded into (s, cc).
// ---------------------------------------------------------------------------
__global__ void __launch_bounds__(256)
gemm_kernel(const float* __restrict__ B, const float* __restrict__ encb,
            float* __restrict__ C) {
    __shared__ float As[2][16][128];
    __shared__ float Bs[2][16][64];

    int tid = threadIdx.x;
    int tx = tid & 15;        // N sub: cols tx*4..tx*4+3
    int ty = tid >> 4;        // M sub: rows ty*8..ty*8+7
    int r1 = tid >> 2;        // 0..63 load row
    int q  = tid & 3;         // k-quad

    const float* Ap  = g_xc + (size_t)(blockIdx.x * 128 + r1) * DIN + q * 4;
    const float* Ap2 = Ap + (size_t)64 * DIN;
    const float* Bp  = B   + (size_t)(blockIdx.y * 64  + r1) * DIN + q * 4;

    float s[8][4], cc[8][4], pb[8][4];
    #pragma unroll
    for (int i = 0; i < 8; i++)
        #pragma unroll
        for (int j = 0; j < 4; j++) { s[i][j] = 0.f; cc[i][j] = 0.f; }

    // prologue: stage 0
    {
        float4 a0 = *(const float4*)(Ap);
        float4 a1 = *(const float4*)(Ap2);
        float4 b0 = *(const float4*)(Bp);
        As[0][q * 4 + 0][r1] = a0.x; As[0][q * 4 + 1][r1] = a0.y;
        As[0][q * 4 + 2][r1] = a0.z; As[0][q * 4 + 3][r1] = a0.w;
        As[0][q * 4 + 0][r1 + 64] = a1.x; As[0][q * 4 + 1][r1 + 64] = a1.y;
        As[0][q * 4 + 2][r1 + 64] = a1.z; As[0][q * 4 + 3][r1 + 64] = a1.w;
        Bs[0][q * 4 + 0][r1] = b0.x; Bs[0][q * 4 + 1][r1] = b0.y;
        Bs[0][q * 4 + 2][r1] = b0.z; Bs[0][q * 4 + 3][r1] = b0.w;
    }
    __syncthreads();

    for (int kb = 0; kb < DIN; kb += 16) {
        int cur = (kb >> 4) & 1;
        int nxt = cur ^ 1;
        if (kb + 16 < DIN) {
            float4 a0 = *(const float4*)(Ap  + kb + 16);
            float4 a1 = *(const float4*)(Ap2 + kb + 16);
            float4 b0 = *(const float4*)(Bp  + kb + 16);
            As[nxt][q * 4 + 0][r1] = a0.x; As[nxt][q * 4 + 1][r1] = a0.y;
            As[nxt][q * 4 + 2][r1] = a0.z; As[nxt][q * 4 + 3][r1] = a0.w;
            As[nxt][q * 4 + 0][r1 + 64] = a1.x; As[nxt][q * 4 + 1][r1 + 64] = a1.y;
            As[nxt][q * 4 + 2][r1 + 64] = a1.z; As[nxt][q * 4 + 3][r1 + 64] = a1.w;
            Bs[nxt][q * 4 + 0][r1] = b0.x; Bs[nxt][q * 4 + 1][r1] = b0.y;
            Bs[nxt][q * 4 + 2][r1] = b0.z; Bs[nxt][q * 4 + 3][r1] = b0.w;
        }

        #pragma unroll
        for (int i = 0; i < 8; i++)
            #pragma unroll
            for (int j = 0; j < 4; j++) pb[i][j] = 0.f;

        #pragma unroll
        for (int k2 = 0; k2 < 16; k2++) {
            float4 av0 = *(const float4*)&As[cur][k2][ty * 8];
            float4 av1 = *(const float4*)&As[cur][k2][ty * 8 + 4];
            float4 bv  = *(const float4*)&Bs[cur][k2][tx * 4];
            float ar[8] = {av0.x, av0.y, av0.z, av0.w,
                           av1.x, av1.y, av1.z, av1.w};
            float br[4] = {bv.x, bv.y, bv.z, bv.w};
            #pragma unroll
            for (int i = 0; i < 8; i++)
                #pragma unroll
                for (int j = 0; j < 4; j++)
                    pb[i][j] += ar[i] * br[j];
        }

        // Kahan fold of this 16-k block sum into (s, cc)
        #pragma unroll
        for (int i = 0; i < 8; i++)
            #pragma unroll
            for (int j = 0; j < 4; j++) {
                float y = pb[i][j] - cc[i][j];
                float t = s[i][j] + y;
                cc[i][j] = (t - s[i][j]) - y;
                s[i][j] = t;
            }
        __syncthreads();
    }

    int f0 = blockIdx.y * 64 + tx * 4;
    float4 e0 = *(const float4*)(encb + f0);
    #pragma unroll
    for (int i = 0; i < 8; i++) {
        size_t off = (size_t)(blockIdx.x * 128 + ty * 8 + i) * NFEAT + f0;
        float4 o;
        o.x = (s[i][0] + cc[i][0]) + e0.x;
        o.y = (s[i][1] + cc[i][1]) + e0.y;
        o.z = (s[i][2] + cc[i][2]) + e0.z;
        o.w = (s[i][3] + cc[i][3]) + e0.w;
        *(float4*)(C + off) = o;
    }
}

// ---------------------------------------------------------------------------
// 4) exact top-k per token (radix select, ties by index)
// ---------------------------------------------------------------------------
__global__ void __launch_bounds__(512)
topk_kernel(float* __restrict__ feats, const int* __restrict__ kp) {
    extern __shared__ uint32_t keys[];
    __shared__ int hist[256];
    __shared__ int s16[16];
    __shared__ int sb[2];
    __shared__ int runs[2];

    int t = blockIdx.x, tid = threadIdx.x;
    int kk = kp ? *kp : 64;
    if (kk < 1) kk = 1;
    if (kk > MAXK) kk = MAXK;

    float* row = feats + (size_t)t * NFEAT;
    for (int i = tid; i < NFEAT; i += 512) keys[i] = f2k(row[i]);
    __syncthreads();

    uint32_t prefix = 0;
    int rem = kk;
    for (int shift = 24; shift >= 0; shift -= 8) {
        if (tid < 256) hist[tid] = 0;
        __syncthreads();
        for (int i = tid; i < NFEAT; i += 512) {
            uint32_t u = keys[i];
            if (shift == 24 || (u >> (shift + 8)) == prefix)
                atomicAdd(&hist[(u >> shift) & 255], 1);
        }
        __syncthreads();
        if (tid == 0) {
            int cum = 0, b = 255;
            for (; b >= 0; b--) { cum += hist[b]; if (cum >= rem) break; }
            sb[0] = b;
            sb[1] = rem - (cum - hist[b]);
        }
        __syncthreads();
        prefix = (prefix << 8) | (uint32_t)sb[0];
        rem = sb[1];
        __syncthreads();
    }
    uint32_t thr = prefix;

    if (tid == 0) { runs[0] = 0; runs[1] = 0; }
    __syncthreads();

    for (int base = 0; base < NFEAT; base += 512) {
        int i = base + tid;
        uint32_t u = keys[i];
        int isEq = (u == thr);
        int isGt = (u > thr);
        int eqEx   = block_exscan512(isEq, s16);
        int kept   = isGt | (isEq & ((runs[0] + eqEx) < rem));
        int keptEx = block_exscan512(kept, s16);
        int slot   = runs[1] + keptEx;
        float v = fmaxf(k2f(u), 0.0f);
        row[i] = kept ? v : 0.0f;
        if (kept && slot < MAXK) {
            g_selIdx[(size_t)t * MAXK + slot] = i;
            g_selVal[(size_t)t * MAXK + slot] = v;
        }
        __syncthreads();
        if (tid == 511) {
            runs[0] += eqEx + isEq;
            runs[1] += keptEx + kept;
        }
        __syncthreads();
    }
}

// ---------------------------------------------------------------------------
// 5) sparse decode + fused loss partial
// ---------------------------------------------------------------------------
__global__ void __launch_bounds__(512)
decode_kernel(float* __restrict__ pred, const float* __restrict__ y,
              const int* __restrict__ kp) {
    int t = blockIdx.x, tid = threadIdx.x;
    int kk = kp ? *kp : 64;
    if (kk < 1) kk = 1;
    if (kk > MAXK) kk = MAXK;

    float4 a0 = make_float4(0.f, 0.f, 0.f, 0.f), a1 = a0;
    const int*   si = g_selIdx + (size_t)t * MAXK;
    const float* sv = g_selVal + (size_t)t * MAXK;

    for (int s = 0; s < kk; s++) {
        int   j = si[s];
        float v = sv[s];
        const float4* r = (const float4*)(g_wT + (size_t)j * DOUTD);
        float4 w0 = r[tid], w1 = r[tid + 512];
        a0.x += v * w0.x; a0.y += v * w0.y; a0.z += v * w0.z; a0.w += v * w0.w;
        a1.x += v * w1.x; a1.y += v * w1.y; a1.z += v * w1.z; a1.w += v * w1.w;
    }

    float4* pr = (float4*)(pred + (size_t)t * DOUTD);
    pr[tid] = a0;
    pr[tid + 512] = a1;

    const float4* yr = (const float4*)(y + (size_t)t * DOUTD);
    float4 y0 = yr[tid], y1 = yr[tid + 512];
    float s2 = 0.f, d;
    d = a0.x - y0.x; s2 += d * d;  d = a0.y - y0.y; s2 += d * d;
    d = a0.z - y0.z; s2 += d * d;  d = a0.w - y0.w; s2 += d * d;
    d = a1.x - y1.x; s2 += d * d;  d = a1.y - y1.y; s2 += d * d;
    d = a1.z - y1.z; s2 += d * d;  d = a1.w - y1.w; s2 += d * d;

    #pragma unroll
    for (int o = 16; o; o >>= 1) s2 += __shfl_down_sync(0xffffffffu, s2, o);
    __shared__ float ws[16];
    int lane = tid & 31, wid = tid >> 5;
    if (lane == 0) ws[wid] = s2;
    __syncthreads();
    if (wid == 0) {
        float v2 = (lane < 16) ? ws[lane] : 0.f;
        #pragma unroll
        for (int o = 8; o; o >>= 1) v2 += __shfl_down_sync(0xffffffffu, v2, o);
        if (lane == 0) g_partial[t] = (double)v2;
    }
}

// ---------------------------------------------------------------------------
// 6) deterministic loss reduction
// ---------------------------------------------------------------------------
__global__ void finalize_kernel(float* __restrict__ scal) {
    __shared__ double sh[256];
    int tid = threadIdx.x;
    double s = 0.0;
    for (int i = tid; i < T_TOK; i += 256) s += g_partial[i];
    sh[tid] = s;
    __syncthreads();
    for (int o = 128; o; o >>= 1) {
        if (tid < o) sh[tid] += sh[tid + o];
        __syncthreads();
    }
    if (tid == 0) {
        float L = (float)(sh[0] / ((double)T_TOK * (double)DOUTD));
        scal[0] = L;
        scal[1] = L;
        scal[2] = 0.0f;
    }
}

// ---------------------------------------------------------------------------
extern "C" void kernel_launch(void* const* d_in, const int* in_sizes, int n_in,
                              void* d_out, int out_size) {
    const float* x    = (const float*)d_in[0];
    const float* y    = (const float*)d_in[1];
    const float* encw = (const float*)d_in[2];
    const float* encb = (const float*)d_in[3];
    const float* decw = (const float*)d_in[4];
    const float* bias = (const float*)d_in[5];
    const int*   kp   = (n_in > 6) ? (const int*)d_in[6] : nullptr;
    (void)in_sizes;

    size_t featN = (size_t)T_TOK * NFEAT;
    size_t predN = (size_t)T_TOK * DOUTD;
    float* out = (float*)d_out;
    size_t osz = (size_t)out_size;

    float *fb_pre = nullptr, *fb_pred = nullptr;
    cudaGetSymbolAddress((void**)&fb_pre,  g_preFB);
    cudaGetSymbolAddress((void**)&fb_pred, g_predFB);

    float* feats;
    float* pred;
    float* scal = nullptr;
    if (osz >= featN + predN) {
        feats = out;
        pred  = out + featN;
        if (osz >= featN + predN + 3) scal = out + featN + predN;
    } else if (osz >= featN) {
        feats = out;
        pred  = fb_pred;
    } else if (osz >= predN) {
        feats = fb_pre;
        pred  = out;
        if (osz >= predN + 3) scal = out + predN;
    } else {
        feats = fb_pre;
        pred  = fb_pred;
    }

    center_kernel<<<2048, 256>>>((const float4*)x, (const float4*)bias);
    transpose_kernel<<<dim3(NFEAT / 32, DOUTD / 32), dim3(32, 8)>>>(decw);
    gemm_kernel<<<dim3(T_TOK / 128, NFEAT / 64), 256>>>(encw, encb, feats);
    cudaFuncSetAttribute(topk_kernel, cudaFuncAttributeMaxDynamicSharedMemorySize,
                         NFEAT * 4);
    topk_kernel<<<T_TOK, 512, NFEAT * 4>>>(feats, kp);
    decode_kernel<<<T_TOK, 512>>>(pred, y, kp);
    if (scal) finalize_kernel<<<1, 256>>>(scal);
}

// round 5
// speedup vs baseline: 5.0550x; 5.0550x over previous
#include <cuda_runtime.h>
#include <cuda_bf16.h>
#include <cstdint>

// ---------------------------------------------------------------------------
// Transcoder: pre = (x - bias) @ enc_w^T + enc_b ; top-k ; sparse decode ; MSE
// Round 5: select-then-refine with BIT-EXACT replication of Round 3's
// accumulation order in the candidate recompute (16-elem FFMA blocks +
// sequential Kahan fold) -> selection identical to the passing R3 kernel.
// ---------------------------------------------------------------------------

#define T_TOK 4096
#define DIN   4096
#define NFEAT 32768
#define DOUTD 4096
#define MAXK  128
#define CAND  128

__device__ float          g_xc[(size_t)T_TOK * DIN];       // centered fp32
__device__ __nv_bfloat16  g_xb[(size_t)T_TOK * DIN];       // centered bf16
__device__ __nv_bfloat16  g_wb[(size_t)NFEAT * DIN];       // enc_w bf16
__device__ float          g_approx[(size_t)T_TOK * NFEAT]; // approx pre
__device__ float          g_wT[(size_t)NFEAT * DOUTD];     // dec_w transposed
__device__ int            g_selIdx[(size_t)T_TOK * MAXK];  // candidates
__device__ float          g_selVal[(size_t)T_TOK * MAXK];  // exact cand vals
__device__ int            g_dIdx[(size_t)T_TOK * MAXK];    // final kept
__device__ float          g_dVal[(size_t)T_TOK * MAXK];
__device__ double         g_partial[T_TOK];
__device__ float          g_preFB[(size_t)T_TOK * NFEAT];  // layout fallbacks
__device__ float          g_predFB[(size_t)T_TOK * DOUTD];

// ---------------------------------------------------------------------------
__device__ __forceinline__ uint32_t f2k(float f) {
    uint32_t u = __float_as_uint(f);
    return (u & 0x80000000u) ? ~u : (u | 0x80000000u);
}

// ---------------------------------------------------------------------------
// 1) center: fp32 + bf16 copies
// ---------------------------------------------------------------------------
__global__ void center_kernel(const float4* __restrict__ x,
                              const float4* __restrict__ bias) {
    size_t n = (size_t)T_TOK * DIN / 4;
    for (size_t i = (size_t)blockIdx.x * blockDim.x + threadIdx.x; i < n;
         i += (size_t)gridDim.x * blockDim.x) {
        float4 a = x[i];
        float4 b = bias[i & (DIN / 4 - 1)];
        float4 r;
        r.x = a.x - b.x; r.y = a.y - b.y; r.z = a.z - b.z; r.w = a.w - b.w;
        ((float4*)g_xc)[i] = r;
        __nv_bfloat162 h0 = __floats2bfloat162_rn(r.x, r.y);
        __nv_bfloat162 h1 = __floats2bfloat162_rn(r.z, r.w);
        uint2 pk;
        pk.x = *(uint32_t*)&h0;
        pk.y = *(uint32_t*)&h1;
        ((uint2*)g_xb)[i] = pk;
    }
}

// ---------------------------------------------------------------------------
// 2) enc_w -> bf16
// ---------------------------------------------------------------------------
__global__ void convertw_kernel(const float4* __restrict__ W) {
    size_t n = (size_t)NFEAT * DIN / 4;
    for (size_t i = (size_t)blockIdx.x * blockDim.x + threadIdx.x; i < n;
         i += (size_t)gridDim.x * blockDim.x) {
        float4 a = W[i];
        __nv_bfloat162 h0 = __floats2bfloat162_rn(a.x, a.y);
        __nv_bfloat162 h1 = __floats2bfloat162_rn(a.z, a.w);
        uint2 pk;
        pk.x = *(uint32_t*)&h0;
        pk.y = *(uint32_t*)&h1;
        ((uint2*)g_wb)[i] = pk;
    }
}

// ---------------------------------------------------------------------------
// 3) transpose dec_w -> g_wT [NFEAT, DOUTD]
// ---------------------------------------------------------------------------
__global__ void transpose_kernel(const float* __restrict__ W) {
    __shared__ float tile[32][33];
    int j0 = blockIdx.x * 32;
    int d0 = blockIdx.y * 32;
    int tx = threadIdx.x, ty0 = threadIdx.y;
    #pragma unroll
    for (int ty = ty0; ty < 32; ty += 8)
        tile[ty][tx] = W[(size_t)(d0 + ty) * NFEAT + j0 + tx];
    __syncthreads();
    #pragma unroll
    for (int ty = ty0; ty < 32; ty += 8)
        g_wT[(size_t)(j0 + ty) * DOUTD + d0 + tx] = tile[tx][ty];
}

// ---------------------------------------------------------------------------
// 4) approx bf16 GEMM via mma.sync.m16n8k16 (unchanged from R4 - verified ok)
// ---------------------------------------------------------------------------
#define GSTR 48   // smem row stride (bf16 units)

__global__ void __launch_bounds__(256)
hgemm_kernel(const float* __restrict__ encb, float* __restrict__ C) {
    __shared__ __nv_bfloat16 sm[2 * 2 * 128 * GSTR];  // [stage][A|B][128][48]

    int tid  = threadIdx.x;
    int lane = tid & 31;
    int warp = tid >> 5;
    int wm   = warp & 1;
    int wn   = warp >> 1;

    int mBase = blockIdx.x * 128;
    int nBase = blockIdx.y * 128;

    int lr = tid >> 2;
    int lc = tid & 3;
    const __nv_bfloat16* pA = g_xb + (size_t)(mBase + lr) * DIN + lc * 8;
    const __nv_bfloat16* pB = g_wb + (size_t)(nBase + lr) * DIN + lc * 8;
    int stoA = lr * GSTR + lc * 8;

    float acc[4][4][4];
    #pragma unroll
    for (int mi = 0; mi < 4; mi++)
        #pragma unroll
        for (int nj = 0; nj < 4; nj++)
            #pragma unroll
            for (int r = 0; r < 4; r++) acc[mi][nj][r] = 0.f;

    {
        uint4 a0 = *(const uint4*)pA;
        uint4 a1 = *(const uint4*)(pA + (size_t)64 * DIN);
        uint4 b0 = *(const uint4*)pB;
        uint4 b1 = *(const uint4*)(pB + (size_t)64 * DIN);
        *(uint4*)&sm[stoA]                    = a0;
        *(uint4*)&sm[stoA + 64 * GSTR]        = a1;
        *(uint4*)&sm[6144 + stoA]             = b0;
        *(uint4*)&sm[6144 + stoA + 64 * GSTR] = b1;
    }
    __syncthreads();

    int aRowL = (lane & 15);
    int aKHL  = (lane >> 4) << 3;
    int bRowL = ((lane >> 4) << 3) + (lane & 7);
    int bKHL  = ((lane >> 3) & 1) << 3;

    int stage = 0;
    for (int kb = 0; kb < DIN; kb += 32) {
        uint4 a0, a1, b0, b1;
        bool has = (kb + 32) < DIN;
        if (has) {
            a0 = *(const uint4*)(pA + kb + 32);
            a1 = *(const uint4*)(pA + kb + 32 + (size_t)64 * DIN);
            b0 = *(const uint4*)(pB + kb + 32);
            b1 = *(const uint4*)(pB + kb + 32 + (size_t)64 * DIN);
        }

        const __nv_bfloat16* smA = sm + stage * 12288;
        const __nv_bfloat16* smB = smA + 6144;

        #pragma unroll
        for (int ks = 0; ks < 32; ks += 16) {
            uint32_t af[4][4];
            #pragma unroll
            for (int mi = 0; mi < 4; mi++) {
                int row = wm * 64 + mi * 16 + aRowL;
                uint32_t sa = (uint32_t)__cvta_generic_to_shared(
                    smA + row * GSTR + ks + aKHL);
                asm volatile(
                    "ldmatrix.sync.aligned.m8n8.x4.shared.b16 {%0,%1,%2,%3}, [%4];"
                    : "=r"(af[mi][0]), "=r"(af[mi][1]),
                      "=r"(af[mi][2]), "=r"(af[mi][3]) : "r"(sa));
            }
            uint32_t bfm[2][4];
            #pragma unroll
            for (int p = 0; p < 2; p++) {
                int row = wn * 32 + p * 16 + bRowL;
                uint32_t sb = (uint32_t)__cvta_generic_to_shared(
                    smB + row * GSTR + ks + bKHL);
                asm volatile(
                    "ldmatrix.sync.aligned.m8n8.x4.shared.b16 {%0,%1,%2,%3}, [%4];"
                    : "=r"(bfm[p][0]), "=r"(bfm[p][1]),
                      "=r"(bfm[p][2]), "=r"(bfm[p][3]) : "r"(sb));
            }
            #pragma unroll
            for (int mi = 0; mi < 4; mi++)
                #pragma unroll
                for (int nj = 0; nj < 4; nj++) {
                    uint32_t bb0 = bfm[nj >> 1][(nj & 1) * 2 + 0];
                    uint32_t bb1 = bfm[nj >> 1][(nj & 1) * 2 + 1];
                    asm volatile(
                        "mma.sync.aligned.m16n8k16.row.col.f32.bf16.bf16.f32 "
                        "{%0,%1,%2,%3}, {%4,%5,%6,%7}, {%8,%9}, {%0,%1,%2,%3};"
                        : "+f"(acc[mi][nj][0]), "+f"(acc[mi][nj][1]),
                          "+f"(acc[mi][nj][2]), "+f"(acc[mi][nj][3])
                        : "r"(af[mi][0]), "r"(af[mi][1]),
                          "r"(af[mi][2]), "r"(af[mi][3]),
                          "r"(bb0), "r"(bb1));
                }
        }

        if (has) {
            __nv_bfloat16* dA = sm + (stage ^ 1) * 12288;
            *(uint4*)&dA[stoA]                    = a0;
            *(uint4*)&dA[stoA + 64 * GSTR]        = a1;
            *(uint4*)&dA[6144 + stoA]             = b0;
            *(uint4*)&dA[6144 + stoA + 64 * GSTR] = b1;
        }
        __syncthreads();
        stage ^= 1;
    }

    #pragma unroll
    for (int mi = 0; mi < 4; mi++) {
        int m0 = mBase + wm * 64 + mi * 16 + (lane >> 2);
        #pragma unroll
        for (int nj = 0; nj < 4; nj++) {
            int col = nBase + wn * 32 + nj * 8 + (lane & 3) * 2;
            float2 e = *(const float2*)(encb + col);
            float2 o0, o1;
            o0.x = acc[mi][nj][0] + e.x; o0.y = acc[mi][nj][1] + e.y;
            o1.x = acc[mi][nj][2] + e.x; o1.y = acc[mi][nj][3] + e.y;
            *(float2*)(C + (size_t)m0 * NFEAT + col)       = o0;
            *(float2*)(C + (size_t)(m0 + 8) * NFEAT + col) = o1;
        }
    }
}

// ---------------------------------------------------------------------------
// 5) candidate select: radix top-CAND of approx row (parallel tie handling)
// ---------------------------------------------------------------------------
__global__ void __launch_bounds__(512)
cand_kernel(const float* __restrict__ approx) {
    extern __shared__ uint32_t keys[];   // NFEAT keys (128 KB)
    __shared__ int hist[256];
    __shared__ int sb[2];
    __shared__ int cnt;
    __shared__ int eqbuf[CAND];
    __shared__ int eqn;

    int t = blockIdx.x, tid = threadIdx.x;
    const float* row = approx + (size_t)t * NFEAT;
    for (int i = tid; i < NFEAT; i += 512) keys[i] = f2k(row[i]);
    __syncthreads();

    uint32_t prefix = 0;
    int rem = CAND;
    for (int shift = 24; shift >= 0; shift -= 8) {
        if (tid < 256) hist[tid] = 0;
        __syncthreads();
        for (int i = tid; i < NFEAT; i += 512) {
            uint32_t u = keys[i];
            if (shift == 24 || (u >> (shift + 8)) == prefix)
                atomicAdd(&hist[(u >> shift) & 255], 1);
        }
        __syncthreads();
        if (tid == 0) {
            int cum = 0, b = 255;
            for (; b >= 0; b--) { cum += hist[b]; if (cum >= rem) break; }
            sb[0] = b;
            sb[1] = rem - (cum - hist[b]);
        }
        __syncthreads();
        prefix = (prefix << 8) | (uint32_t)sb[0];
        rem = sb[1];
        __syncthreads();
    }
    uint32_t thr = prefix;   // key of CAND-th largest; rem = #ties to keep

    if (tid == 0) { cnt = 0; eqn = 0; }
    __syncthreads();
    for (int i = tid; i < NFEAT; i += 512) {
        uint32_t u = keys[i];
        if (u > thr) {
            int s = atomicAdd(&cnt, 1);
            g_selIdx[(size_t)t * MAXK + s] = i;
        } else if (u == thr) {
            int s = atomicAdd(&eqn, 1);
            if (s < CAND) eqbuf[s] = i;
        }
    }
    __syncthreads();
    if (tid == 0) {
        int n = eqn < CAND ? eqn : CAND;
        int base = cnt;
        for (int r = 0; r < rem; r++) {       // take rem smallest indices
            int best = 0x7fffffff, bi = -1;
            for (int q = 0; q < n; q++)
                if (eqbuf[q] < best) { best = eqbuf[q]; bi = q; }
            if (bi < 0) break;
            eqbuf[bi] = 0x7fffffff;
            g_selIdx[(size_t)t * MAXK + base + r] = best;
        }
    }
}

// ---------------------------------------------------------------------------
// 6) exact recompute of candidates, BIT-IDENTICAL to R3's GEMM accumulation:
//    16-elem sequential FFMA block sums (k ascending), Kahan fold of the 256
//    block sums in ascending order, then (s+cc)+enc_b.
//    One warp per candidate: lanes make 8 block sums each; lane 0 folds.
// ---------------------------------------------------------------------------
__global__ void __launch_bounds__(512)
recompute_kernel(const float* __restrict__ encw, const float* __restrict__ encb) {
    __shared__ float xs[DIN];          // 16 KB
    __shared__ float bs[16][256];      // 16 KB
    int t = blockIdx.x, tid = threadIdx.x;
    int lane = tid & 31, w = tid >> 5;

    const float4* xr = (const float4*)(g_xc + (size_t)t * DIN);
    for (int i = tid; i < DIN / 4; i += 512) ((float4*)xs)[i] = xr[i];
    __syncthreads();

    #pragma unroll 1
    for (int g = 0; g < CAND / 16; g++) {
        int c = w + 16 * g;
        int j = g_selIdx[(size_t)t * MAXK + c];
        const float* wr = encw + (size_t)j * DIN;

        #pragma unroll 1
        for (int bb = 0; bb < 8; bb++) {
            int b = lane + 32 * bb;
            int k0 = b * 16;
            float pb = 0.f;
            #pragma unroll
            for (int u = 0; u < 4; u++) {
                float4 wv = *(const float4*)(wr + k0 + u * 4);
                float4 xv = *(const float4*)(xs + k0 + u * 4);
                pb = fmaf(xv.x, wv.x, pb);
                pb = fmaf(xv.y, wv.y, pb);
                pb = fmaf(xv.z, wv.z, pb);
                pb = fmaf(xv.w, wv.w, pb);
            }
            bs[w][b] = pb;
        }
        __syncwarp();
        if (lane == 0) {
            float s = 0.f, cc = 0.f;
            #pragma unroll 8
            for (int b = 0; b < 256; b++) {
                float y  = bs[w][b] - cc;
                float tt = s + y;
                cc = (tt - s) - y;
                s = tt;
            }
            g_selVal[(size_t)t * MAXK + c] = (s + cc) + encb[j];
        }
        __syncwarp();
    }
}

// ---------------------------------------------------------------------------
// 7) zero features region
// ---------------------------------------------------------------------------
__global__ void zero_kernel(float4* __restrict__ p, size_t n4) {
    for (size_t i = (size_t)blockIdx.x * blockDim.x + threadIdx.x; i < n4;
         i += (size_t)gridDim.x * blockDim.x)
        p[i] = make_float4(0.f, 0.f, 0.f, 0.f);
}

// ---------------------------------------------------------------------------
// 8) final select among candidates (exact rank, ties by index) + scatter
// ---------------------------------------------------------------------------
__global__ void __launch_bounds__(CAND)
select_kernel(float* __restrict__ feats, const int* __restrict__ kp) {
    __shared__ float sv[CAND];
    __shared__ int   sj[CAND];
    __shared__ int   cnt;
    int t = blockIdx.x, c = threadIdx.x;
    int kk = kp ? *kp : 64;
    if (kk < 1) kk = 1;
    if (kk > CAND) kk = CAND;

    float v = g_selVal[(size_t)t * MAXK + c];
    int   j = g_selIdx[(size_t)t * MAXK + c];
    sv[c] = v; sj[c] = j;
    if (c == 0) cnt = 0;
    __syncthreads();

    int rank = 0;
    #pragma unroll 8
    for (int o = 0; o < CAND; o++)
        rank += (sv[o] > v) || (sv[o] == v && sj[o] < j);

    if (rank < kk) {
        int s = atomicAdd(&cnt, 1);
        float rv = fmaxf(v, 0.f);
        g_dIdx[(size_t)t * MAXK + s] = j;
        g_dVal[(size_t)t * MAXK + s] = rv;
        feats[(size_t)t * NFEAT + j] = rv;
    }
}

// ---------------------------------------------------------------------------
// 9) sparse decode + fused loss partial
// ---------------------------------------------------------------------------
__global__ void __launch_bounds__(512)
decode_kernel(float* __restrict__ pred, const float* __restrict__ y,
              const int* __restrict__ kp) {
    int t = blockIdx.x, tid = threadIdx.x;
    int kk = kp ? *kp : 64;
    if (kk < 1) kk = 1;
    if (kk > CAND) kk = CAND;

    float4 a0 = make_float4(0.f, 0.f, 0.f, 0.f), a1 = a0;
    const int*   si = g_dIdx + (size_t)t * MAXK;
    const float* sv = g_dVal + (size_t)t * MAXK;

    for (int s = 0; s < kk; s++) {
        int   j = si[s];
        float v = sv[s];
        const float4* r = (const float4*)(g_wT + (size_t)j * DOUTD);
        float4 w0 = r[tid], w1 = r[tid + 512];
        a0.x += v * w0.x; a0.y += v * w0.y; a0.z += v * w0.z; a0.w += v * w0.w;
        a1.x += v * w1.x; a1.y += v * w1.y; a1.z += v * w1.z; a1.w += v * w1.w;
    }

    float4* pr = (float4*)(pred + (size_t)t * DOUTD);
    pr[tid] = a0;
    pr[tid + 512] = a1;

    const float4* yr = (const float4*)(y + (size_t)t * DOUTD);
    float4 y0 = yr[tid], y1 = yr[tid + 512];
    float s2 = 0.f, d;
    d = a0.x - y0.x; s2 += d * d;  d = a0.y - y0.y; s2 += d * d;
    d = a0.z - y0.z; s2 += d * d;  d = a0.w - y0.w; s2 += d * d;
    d = a1.x - y1.x; s2 += d * d;  d = a1.y - y1.y; s2 += d * d;
    d = a1.z - y1.z; s2 += d * d;  d = a1.w - y1.w; s2 += d * d;

    #pragma unroll
    for (int o = 16; o; o >>= 1) s2 += __shfl_down_sync(0xffffffffu, s2, o);
    __shared__ float ws[16];
    int lane = tid & 31, wid = tid >> 5;
    if (lane == 0) ws[wid] = s2;
    __syncthreads();
    if (wid == 0) {
        float v2 = (lane < 16) ? ws[lane] : 0.f;
        #pragma unroll
        for (int o = 8; o; o >>= 1) v2 += __shfl_down_sync(0xffffffffu, v2, o);
        if (lane == 0) g_partial[t] = (double)v2;
    }
}

// ---------------------------------------------------------------------------
// 10) deterministic loss reduction
// ---------------------------------------------------------------------------
__global__ void finalize_kernel(float* __restrict__ scal) {
    __shared__ double sh[256];
    int tid = threadIdx.x;
    double s = 0.0;
    for (int i = tid; i < T_TOK; i += 256) s += g_partial[i];
    sh[tid] = s;
    __syncthreads();
    for (int o = 128; o; o >>= 1) {
        if (tid < o) sh[tid] += sh[tid + o];
        __syncthreads();
    }
    if (tid == 0) {
        float L = (float)(sh[0] / ((double)T_TOK * (double)DOUTD));
        scal[0] = L;
        scal[1] = L;
        scal[2] = 0.0f;
    }
}

// ---------------------------------------------------------------------------
extern "C" void kernel_launch(void* const* d_in, const int* in_sizes, int n_in,
                              void* d_out, int out_size) {
    const float* x    = (const float*)d_in[0];
    const float* y    = (const float*)d_in[1];
    const float* encw = (const float*)d_in[2];
    const float* encb = (const float*)d_in[3];
    const float* decw = (const float*)d_in[4];
    const float* bias = (const float*)d_in[5];
    const int*   kp   = (n_in > 6) ? (const int*)d_in[6] : nullptr;
    (void)in_sizes;

    size_t featN = (size_t)T_TOK * NFEAT;
    size_t predN = (size_t)T_TOK * DOUTD;
    float* out = (float*)d_out;
    size_t osz = (size_t)out_size;

    float *fb_pre = nullptr, *fb_pred = nullptr;
    cudaGetSymbolAddress((void**)&fb_pre,  g_preFB);
    cudaGetSymbolAddress((void**)&fb_pred, g_predFB);

    float* feats;
    float* pred;
    float* scal = nullptr;
    if (osz >= featN + predN) {
        feats = out;
        pred  = out + featN;
        if (osz >= featN + predN + 3) scal = out + featN + predN;
    } else if (osz >= featN) {
        feats = out;
        pred  = fb_pred;
    } else if (osz >= predN) {
        feats = fb_pre;
        pred  = out;
        if (osz >= predN + 3) scal = out + predN;
    } else {
        feats = fb_pre;
        pred  = fb_pred;
    }

    float* approx = nullptr;
    cudaGetSymbolAddress((void**)&approx, g_approx);

    center_kernel<<<2048, 256>>>((const float4*)x, (const float4*)bias);
    convertw_kernel<<<4096, 256>>>((const float4*)encw);
    transpose_kernel<<<dim3(NFEAT / 32, DOUTD / 32), dim3(32, 8)>>>(decw);
    hgemm_kernel<<<dim3(T_TOK / 128, NFEAT / 128), 256>>>(encb, approx);
    cudaFuncSetAttribute(cand_kernel, cudaFuncAttributeMaxDynamicSharedMemorySize,
                         NFEAT * 4);
    cand_kernel<<<T_TOK, 512, NFEAT * 4>>>(approx);
    recompute_kernel<<<T_TOK, 512>>>(encw, encb);
    zero_kernel<<<8192, 256>>>((float4*)feats, featN / 4);
    select_kernel<<<T_TOK, CAND>>>(feats, kp);
    decode_kernel<<<T_TOK, 512>>>(pred, y, kp);
    if (scal) finalize_kernel<<<1, 256>>>(scal);
}

// round 7
// speedup vs baseline: 7.1756x; 1.4195x over previous
#include <cuda_runtime.h>
#include <cuda_bf16.h>
#include <cstdint>

// ---------------------------------------------------------------------------
// Transcoder: pre = (x - bias) @ enc_w^T + enc_b ; top-k ; sparse decode ; MSE
// Round 7: HMMA (mma.sync) approx GEMM with 64x64 warp tiles + cp.async,
// bf16 approx output, 16-bit radix candidate select (CAND=96), bit-exact
// Kahan recompute (R3-identical order). tcgen05 unavailable (sm_103 target).
// ---------------------------------------------------------------------------

#define T_TOK 4096
#define DIN   4096
#define NFEAT 32768
#define DOUTD 4096
#define MAXK  128
#define CAND  96

__device__ float          g_xc[(size_t)T_TOK * DIN];        // centered fp32
__device__ __nv_bfloat16  g_xb[(size_t)T_TOK * DIN];        // centered bf16
__device__ __nv_bfloat16  g_wb[(size_t)NFEAT * DIN];        // enc_w bf16
__device__ __nv_bfloat16  g_approxh[(size_t)T_TOK * NFEAT]; // approx pre (bf16)
__device__ float          g_wT[(size_t)NFEAT * DOUTD];      // dec_w transposed
__device__ int            g_selIdx[(size_t)T_TOK * MAXK];
__device__ float          g_selVal[(size_t)T_TOK * MAXK];
__device__ int            g_dIdx[(size_t)T_TOK * MAXK];
__device__ float          g_dVal[(size_t)T_TOK * MAXK];
__device__ double         g_partial[T_TOK];
__device__ float          g_preFB[(size_t)T_TOK * NFEAT];
__device__ float          g_predFB[(size_t)T_TOK * DOUTD];

#define CPASYNC16(dst, src) \
    asm volatile("cp.async.cg.shared.global [%0], [%1], 16;" \
                 :: "r"(dst), "l"(src) : "memory")

// ---------------------------------------------------------------------------
// 1) center: fp32 + bf16 copies
// ---------------------------------------------------------------------------
__global__ void center_kernel(const float4* __restrict__ x,
                              const float4* __restrict__ bias) {
    size_t n = (size_t)T_TOK * DIN / 4;
    for (size_t i = (size_t)blockIdx.x * blockDim.x + threadIdx.x; i < n;
         i += (size_t)gridDim.x * blockDim.x) {
        float4 a = x[i];
        float4 b = bias[i & (DIN / 4 - 1)];
        float4 r;
        r.x = a.x - b.x; r.y = a.y - b.y; r.z = a.z - b.z; r.w = a.w - b.w;
        ((float4*)g_xc)[i] = r;
        __nv_bfloat162 h0 = __floats2bfloat162_rn(r.x, r.y);
        __nv_bfloat162 h1 = __floats2bfloat162_rn(r.z, r.w);
        uint2 pk;
        pk.x = *(uint32_t*)&h0;
        pk.y = *(uint32_t*)&h1;
        ((uint2*)g_xb)[i] = pk;
    }
}

// ---------------------------------------------------------------------------
// 2) enc_w -> bf16
// ---------------------------------------------------------------------------
__global__ void convertw_kernel(const float4* __restrict__ W) {
    size_t n = (size_t)NFEAT * DIN / 4;
    for (size_t i = (size_t)blockIdx.x * blockDim.x + threadIdx.x; i < n;
         i += (size_t)gridDim.x * blockDim.x) {
        float4 a = W[i];
        __nv_bfloat162 h0 = __floats2bfloat162_rn(a.x, a.y);
        __nv_bfloat162 h1 = __floats2bfloat162_rn(a.z, a.w);
        uint2 pk;
        pk.x = *(uint32_t*)&h0;
        pk.y = *(uint32_t*)&h1;
        ((uint2*)g_wb)[i] = pk;
    }
}

// ---------------------------------------------------------------------------
// 3) transpose dec_w -> g_wT [NFEAT, DOUTD]
// ---------------------------------------------------------------------------
__global__ void transpose_kernel(const float* __restrict__ W) {
    __shared__ float tile[32][33];
    int j0 = blockIdx.x * 32;
    int d0 = blockIdx.y * 32;
    int tx = threadIdx.x, ty0 = threadIdx.y;
    #pragma unroll
    for (int ty = ty0; ty < 32; ty += 8)
        tile[ty][tx] = W[(size_t)(d0 + ty) * NFEAT + j0 + tx];
    __syncthreads();
    #pragma unroll
    for (int ty = ty0; ty < 32; ty += 8)
        g_wT[(size_t)(j0 + ty) * DOUTD + d0 + tx] = tile[tx][ty];
}

// ---------------------------------------------------------------------------
// 4) HMMA approx GEMM: approx[t,f] = bf16(xb[t,:].wb[f,:] + encb[f])
//    CTA 128x256, BK=32, 8 warps (2m x 4n), warp tile 64x64, cp.async
//    double buffer. smem row stride 40 bf16 (80B): conflict-free ldmatrix.
// ---------------------------------------------------------------------------
#define RSTR   80                      // bytes per smem row (32 bf16 + pad)
#define A_SZ   (128 * RSTR)            // 10240 B
#define B_SZ   (256 * RSTR)            // 20480 B
#define STG_SZ (A_SZ + B_SZ)           // 30720 B
#define HG_SMEM (2 * STG_SZ)           // 61440 B

__global__ void __launch_bounds__(256)
hgemm_kernel(const float* __restrict__ encb, __nv_bfloat16* __restrict__ C) {
    extern __shared__ char smem[];
    uint32_t sbase;
    asm("{ .reg .u64 t; cvta.to.shared.u64 t, %1; cvt.u32.u64 %0, t; }"
        : "=r"(sbase) : "l"(smem));

    int tid  = threadIdx.x;
    int lane = tid & 31;
    int warp = tid >> 5;
    int wm   = warp & 1;          // 0..1
    int wn   = warp >> 1;         // 0..3

    int mBase = blockIdx.x * 128;
    int nBase = blockIdx.y * 256;

    const __nv_bfloat16* gA0 = g_xb + (size_t)mBase * DIN;
    const __nv_bfloat16* gB0 = g_wb + (size_t)nBase * DIN;

    float acc[4][8][4];
    #pragma unroll
    for (int mi = 0; mi < 4; mi++)
        #pragma unroll
        for (int nj = 0; nj < 8; nj++)
            #pragma unroll
            for (int r = 0; r < 4; r++) acc[mi][nj][r] = 0.f;

    // loader: stage s <- k offset kb
    int lr = tid >> 2, lq = tid & 3;
    auto load_stage = [&](int kb, int s) {
        uint32_t aB = sbase + s * STG_SZ;
        uint32_t bB = aB + A_SZ;
        #pragma unroll
        for (int i = 0; i < 2; i++) {             // A: 512 chunks
            int r = lr + i * 64;
            const __nv_bfloat16* src = gA0 + (size_t)r * DIN + kb + lq * 8;
            CPASYNC16(aB + r * RSTR + lq * 16, src);
        }
        #pragma unroll
        for (int i = 0; i < 4; i++) {             // B: 1024 chunks
            int r = lr + i * 64;
            const __nv_bfloat16* src = gB0 + (size_t)r * DIN + kb + lq * 8;
            CPASYNC16(bB + r * RSTR + lq * 16, src);
        }
        asm volatile("cp.async.commit_group;" ::: "memory");
    };

    load_stage(0, 0);
    asm volatile("cp.async.wait_group 0;" ::: "memory");
    __syncthreads();

    // per-lane ldmatrix components
    int aRow = (lane & 15);
    int aKB  = (lane >> 4) * 16;            // bytes
    int bRow = ((lane >> 4) << 3) + (lane & 7);
    int bKB  = ((lane >> 3) & 1) * 16;      // bytes

    for (int kb = 0; kb < DIN; kb += 32) {
        int s = (kb >> 5) & 1;
        bool has = (kb + 32) < DIN;
        if (has) load_stage(kb + 32, s ^ 1);

        uint32_t aB = sbase + s * STG_SZ;
        uint32_t bB = aB + A_SZ;

        #pragma unroll
        for (int ks = 0; ks < 2; ks++) {          // two k16 slices
            uint32_t af[4][4];
            #pragma unroll
            for (int mi = 0; mi < 4; mi++) {
                int row = wm * 64 + mi * 16 + aRow;
                uint32_t sa = aB + row * RSTR + ks * 32 + aKB;
                asm volatile(
                    "ldmatrix.sync.aligned.m8n8.x4.shared.b16 {%0,%1,%2,%3}, [%4];"
                    : "=r"(af[mi][0]), "=r"(af[mi][1]),
                      "=r"(af[mi][2]), "=r"(af[mi][3]) : "r"(sa));
            }
            uint32_t bf[4][4];
            #pragma unroll
            for (int p = 0; p < 4; p++) {
                int row = wn * 64 + p * 16 + bRow;
                uint32_t sb = bB + row * RSTR + ks * 32 + bKB;
                asm volatile(
                    "ldmatrix.sync.aligned.m8n8.x4.shared.b16 {%0,%1,%2,%3}, [%4];"
                    : "=r"(bf[p][0]), "=r"(bf[p][1]),
                      "=r"(bf[p][2]), "=r"(bf[p][3]) : "r"(sb));
            }
            #pragma unroll
            for (int mi = 0; mi < 4; mi++)
                #pragma unroll
                for (int nj = 0; nj < 8; nj++) {
                    uint32_t b0 = bf[nj >> 1][(nj & 1) * 2 + 0];
                    uint32_t b1 = bf[nj >> 1][(nj & 1) * 2 + 1];
                    asm volatile(
                        "mma.sync.aligned.m16n8k16.row.col.f32.bf16.bf16.f32 "
                        "{%0,%1,%2,%3}, {%4,%5,%6,%7}, {%8,%9}, {%0,%1,%2,%3};"
                        : "+f"(acc[mi][nj][0]), "+f"(acc[mi][nj][1]),
                          "+f"(acc[mi][nj][2]), "+f"(acc[mi][nj][3])
                        : "r"(af[mi][0]), "r"(af[mi][1]),
                          "r"(af[mi][2]), "r"(af[mi][3]),
                          "r"(b0), "r"(b1));
                }
        }

        if (has) asm volatile("cp.async.wait_group 0;" ::: "memory");
        __syncthreads();
    }

    // epilogue: add enc_b, convert to bf16, store
    #pragma unroll
    for (int mi = 0; mi < 4; mi++) {
        int m0 = mBase + wm * 64 + mi * 16 + (lane >> 2);
        #pragma unroll
        for (int nj = 0; nj < 8; nj++) {
            int col = nBase + wn * 64 + nj * 8 + (lane & 3) * 2;
            float2 e = *(const float2*)(encb + col);
            __nv_bfloat162 h0 = __floats2bfloat162_rn(acc[mi][nj][0] + e.x,
                                                      acc[mi][nj][1] + e.y);
            __nv_bfloat162 h1 = __floats2bfloat162_rn(acc[mi][nj][2] + e.x,
                                                      acc[mi][nj][3] + e.y);
            *(uint32_t*)(C + (size_t)m0 * NFEAT + col)       = *(uint32_t*)&h0;
            *(uint32_t*)(C + (size_t)(m0 + 8) * NFEAT + col) = *(uint32_t*)&h1;
        }
    }
}

// ---------------------------------------------------------------------------
// 5) candidate select: 2-pass radix top-CAND over bf16 approx row
// ---------------------------------------------------------------------------
__global__ void __launch_bounds__(512)
cand_kernel(const __nv_bfloat16* __restrict__ approx) {
    extern __shared__ uint16_t keys16[];    // NFEAT uint16 (64 KB)
    __shared__ int hist[256];
    __shared__ int sb[2];
    __shared__ int cnt;
    __shared__ int eqbuf[CAND];
    __shared__ int eqn;

    int t = blockIdx.x, tid = threadIdx.x;
    const uint32_t* row = (const uint32_t*)(approx + (size_t)t * NFEAT);
    for (int i = tid; i < NFEAT / 2; i += 512) {
        uint32_t v = row[i];
        uint16_t a = (uint16_t)v, b = (uint16_t)(v >> 16);
        keys16[2 * i]     = (a & 0x8000) ? (uint16_t)~a : (uint16_t)(a | 0x8000);
        keys16[2 * i + 1] = (b & 0x8000) ? (uint16_t)~b : (uint16_t)(b | 0x8000);
    }
    __syncthreads();

    if (tid < 256) hist[tid] = 0;
    __syncthreads();
    for (int i = tid; i < NFEAT; i += 512)
        atomicAdd(&hist[keys16[i] >> 8], 1);
    __syncthreads();
    if (tid == 0) {
        int cum = 0, b = 255;
        for (; b >= 0; b--) { cum += hist[b]; if (cum >= CAND) break; }
        sb[0] = b;
        sb[1] = CAND - (cum - hist[b]);
    }
    __syncthreads();
    int hb = sb[0];
    int rem = sb[1];
    __syncthreads();

    if (tid < 256) hist[tid] = 0;
    __syncthreads();
    for (int i = tid; i < NFEAT; i += 512) {
        uint16_t u = keys16[i];
        if ((int)(u >> 8) == hb) atomicAdd(&hist[u & 255], 1);
    }
    __syncthreads();
    if (tid == 0) {
        int cum = 0, b = 255;
        for (; b >= 0; b--) { cum += hist[b]; if (cum >= rem) break; }
        sb[0] = b;
        sb[1] = rem - (cum - hist[b]);
    }
    __syncthreads();
    uint16_t thr = (uint16_t)((hb << 8) | sb[0]);
    rem = sb[1];

    if (tid == 0) { cnt = 0; eqn = 0; }
    __syncthreads();
    for (int i = tid; i < NFEAT; i += 512) {
        uint16_t u = keys16[i];
        if (u > thr) {
            int s = atomicAdd(&cnt, 1);
            g_selIdx[(size_t)t * MAXK + s] = i;
        } else if (u == thr) {
            int s = atomicAdd(&eqn, 1);
            if (s < CAND) eqbuf[s] = i;
        }
    }
    __syncthreads();
    if (tid == 0) {
        int n = eqn < CAND ? eqn : CAND;
        int base = cnt;
        for (int r2 = 0; r2 < rem; r2++) {
            int best = 0x7fffffff, bi = -1;
            for (int q = 0; q < n; q++)
                if (eqbuf[q] < best) { best = eqbuf[q]; bi = q; }
            if (bi < 0) break;
            eqbuf[bi] = 0x7fffffff;
            g_selIdx[(size_t)t * MAXK + base + r2] = best;
        }
    }
}

// ---------------------------------------------------------------------------
// 6) exact recompute of candidates, BIT-IDENTICAL to R3 GEMM accumulation
// ---------------------------------------------------------------------------
__global__ void __launch_bounds__(512)
recompute_kernel(const float* __restrict__ encw, const float* __restrict__ encb) {
    __shared__ float xs[DIN];
    __shared__ float bs[16][256];
    int t = blockIdx.x, tid = threadIdx.x;
    int lane = tid & 31, w = tid >> 5;

    const float4* xr = (const float4*)(g_xc + (size_t)t * DIN);
    for (int i = tid; i < DIN / 4; i += 512) ((float4*)xs)[i] = xr[i];
    __syncthreads();

    #pragma unroll 1
    for (int g = 0; g < CAND / 16; g++) {
        int c = w + 16 * g;
        int j = g_selIdx[(size_t)t * MAXK + c];
        const float* wr = encw + (size_t)j * DIN;

        #pragma unroll 1
        for (int bb = 0; bb < 8; bb++) {
            int b = lane + 32 * bb;
            int k0 = b * 16;
            float pb = 0.f;
            #pragma unroll
            for (int u = 0; u < 4; u++) {
                float4 wv = *(const float4*)(wr + k0 + u * 4);
                float4 xv = *(const float4*)(xs + k0 + u * 4);
                pb = fmaf(xv.x, wv.x, pb);
                pb = fmaf(xv.y, wv.y, pb);
                pb = fmaf(xv.z, wv.z, pb);
                pb = fmaf(xv.w, wv.w, pb);
            }
            bs[w][b] = pb;
        }
        __syncwarp();
        if (lane == 0) {
            float s = 0.f, cc = 0.f;
            #pragma unroll 8
            for (int b = 0; b < 256; b++) {
                float y  = bs[w][b] - cc;
                float tt = s + y;
                cc = (tt - s) - y;
                s = tt;
            }
            g_selVal[(size_t)t * MAXK + c] = (s + cc) + encb[j];
        }
        __syncwarp();
    }
}

// ---------------------------------------------------------------------------
// 7) zero features region
// ---------------------------------------------------------------------------
__global__ void zero_kernel(float4* __restrict__ p, size_t n4) {
    for (size_t i = (size_t)blockIdx.x * blockDim.x + threadIdx.x; i < n4;
         i += (size_t)gridDim.x * blockDim.x)
        p[i] = make_float4(0.f, 0.f, 0.f, 0.f);
}

// ---------------------------------------------------------------------------
// 8) final select among candidates (exact rank, ties by index) + scatter
// ---------------------------------------------------------------------------
__global__ void __launch_bounds__(CAND)
select_kernel(float* __restrict__ feats, const int* __restrict__ kp) {
    __shared__ float sv[CAND];
    __shared__ int   sj[CAND];
    __shared__ int   cnt;
    int t = blockIdx.x, c = threadIdx.x;
    int kk = kp ? *kp : 64;
    if (kk < 1) kk = 1;
    if (kk > CAND) kk = CAND;

    float v = g_selVal[(size_t)t * MAXK + c];
    int   j = g_selIdx[(size_t)t * MAXK + c];
    sv[c] = v; sj[c] = j;
    if (c == 0) cnt = 0;
    __syncthreads();

    int rank = 0;
    #pragma unroll 8
    for (int o = 0; o < CAND; o++)
        rank += (sv[o] > v) || (sv[o] == v && sj[o] < j);

    if (rank < kk) {
        int s = atomicAdd(&cnt, 1);
        float rv = fmaxf(v, 0.f);
        g_dIdx[(size_t)t * MAXK + s] = j;
        g_dVal[(size_t)t * MAXK + s] = rv;
        feats[(size_t)t * NFEAT + j] = rv;
    }
}

// ---------------------------------------------------------------------------
// 9) sparse decode + fused loss partial
// ---------------------------------------------------------------------------
__global__ void __launch_bounds__(512)
decode_kernel(float* __restrict__ pred, const float* __restrict__ y,
              const int* __restrict__ kp) {
    int t = blockIdx.x, tid = threadIdx.x;
    int kk = kp ? *kp : 64;
    if (kk < 1) kk = 1;
    if (kk > CAND) kk = CAND;

    float4 a0 = make_float4(0.f, 0.f, 0.f, 0.f), a1 = a0;
    const int*   si = g_dIdx + (size_t)t * MAXK;
    const float* sv = g_dVal + (size_t)t * MAXK;

    for (int s = 0; s < kk; s++) {
        int   j = si[s];
        float v = sv[s];
        const float4* r = (const float4*)(g_wT + (size_t)j * DOUTD);
        float4 w0 = r[tid], w1 = r[tid + 512];
        a0.x += v * w0.x; a0.y += v * w0.y; a0.z += v * w0.z; a0.w += v * w0.w;
        a1.x += v * w1.x; a1.y += v * w1.y; a1.z += v * w1.z; a1.w += v * w1.w;
    }

    float4* pr = (float4*)(pred + (size_t)t * DOUTD);
    pr[tid] = a0;
    pr[tid + 512] = a1;

    const float4* yr = (const float4*)(y + (size_t)t * DOUTD);
    float4 y0 = yr[tid], y1 = yr[tid + 512];
    float s2 = 0.f, d;
    d = a0.x - y0.x; s2 += d * d;  d = a0.y - y0.y; s2 += d * d;
    d = a0.z - y0.z; s2 += d * d;  d = a0.w - y0.w; s2 += d * d;
    d = a1.x - y1.x; s2 += d * d;  d = a1.y - y1.y; s2 += d * d;
    d = a1.z - y1.z; s2 += d * d;  d = a1.w - y1.w; s2 += d * d;

    #pragma unroll
    for (int o = 16; o; o >>= 1) s2 += __shfl_down_sync(0xffffffffu, s2, o);
    __shared__ float ws[16];
    int lane = tid & 31, wid = tid >> 5;
    if (lane == 0) ws[wid] = s2;
    __syncthreads();
    if (wid == 0) {
        float v2 = (lane < 16) ? ws[lane] : 0.f;
        #pragma unroll
        for (int o = 8; o; o >>= 1) v2 += __shfl_down_sync(0xffffffffu, v2, o);
        if (lane == 0) g_partial[t] = (double)v2;
    }
}

// ---------------------------------------------------------------------------
// 10) deterministic loss reduction
// ---------------------------------------------------------------------------
__global__ void finalize_kernel(float* __restrict__ scal) {
    __shared__ double sh[256];
    int tid = threadIdx.x;
    double s = 0.0;
    for (int i = tid; i < T_TOK; i += 256) s += g_partial[i];
    sh[tid] = s;
    __syncthreads();
    for (int o = 128; o; o >>= 1) {
        if (tid < o) sh[tid] += sh[tid + o];
        __syncthreads();
    }
    if (tid == 0) {
        float L = (float)(sh[0] / ((double)T_TOK * (double)DOUTD));
        scal[0] = L;
        scal[1] = L;
        scal[2] = 0.0f;
    }
}

// ---------------------------------------------------------------------------
extern "C" void kernel_launch(void* const* d_in, const int* in_sizes, int n_in,
                              void* d_out, int out_size) {
    const float* x    = (const float*)d_in[0];
    const float* y    = (const float*)d_in[1];
    const float* encw = (const float*)d_in[2];
    const float* encb = (const float*)d_in[3];
    const float* decw = (const float*)d_in[4];
    const float* bias = (const float*)d_in[5];
    const int*   kp   = (n_in > 6) ? (const int*)d_in[6] : nullptr;
    (void)in_sizes;

    size_t featN = (size_t)T_TOK * NFEAT;
    size_t predN = (size_t)T_TOK * DOUTD;
    float* out = (float*)d_out;
    size_t osz = (size_t)out_size;

    float *fb_pre = nullptr, *fb_pred = nullptr;
    cudaGetSymbolAddress((void**)&fb_pre,  g_preFB);
    cudaGetSymbolAddress((void**)&fb_pred, g_predFB);

    float* feats;
    float* pred;
    float* scal = nullptr;
    if (osz >= featN + predN) {
        feats = out;
        pred  = out + featN;
        if (osz >= featN + predN + 3) scal = out + featN + predN;
    } else if (osz >= featN) {
        feats = out;
        pred  = fb_pred;
    } else if (osz >= predN) {
        feats = fb_pre;
        pred  = out;
        if (osz >= predN + 3) scal = out + predN;
    } else {
        feats = fb_pre;
        pred  = fb_pred;
    }

    __nv_bfloat16* approxh = nullptr;
    cudaGetSymbolAddress((void**)&approxh, g_approxh);

    center_kernel<<<2048, 256>>>((const float4*)x, (const float4*)bias);
    convertw_kernel<<<4096, 256>>>((const float4*)encw);
    transpose_kernel<<<dim3(NFEAT / 32, DOUTD / 32), dim3(32, 8)>>>(decw);

    cudaFuncSetAttribute(hgemm_kernel,
                         cudaFuncAttributeMaxDynamicSharedMemorySize, HG_SMEM);
    hgemm_kernel<<<dim3(T_TOK / 128, NFEAT / 256), 256, HG_SMEM>>>(encb, approxh);

    cudaFuncSetAttribute(cand_kernel,
                         cudaFuncAttributeMaxDynamicSharedMemorySize, NFEAT * 2);
    cand_kernel<<<T_TOK, 512, NFEAT * 2>>>(approxh);

    recompute_kernel<<<T_TOK, 512>>>(encw, encb);
    zero_kernel<<<8192, 256>>>((float4*)feats, featN / 4);
    select_kernel<<<T_TOK, CAND>>>(feats, kp);
    decode_kernel<<<T_TOK, 512>>>(pred, y, kp);
    if (scal) finalize_kernel<<<1, 256>>>(scal);
}